// round 1
// baseline (speedup 1.0000x reference)
#include <cuda_runtime.h>

#define NN 50000
#define NE 800000
#define LD 128
#define FED 32
#define TR 64
#define NT 256
#define NB_NODE ((NN + TR - 1) / TR)
#define NB_EDGE (NE / TR)

// Scratch (device globals: allocation is banned)
__device__ float g_inl[NN * LD];        // node linear features
__device__ float g_im[NE * LD];         // input_message
__device__ float g_curW[NE * LD];       // cur @ conv_W
__device__ float g_agg[NN * LD];        // segment-sum accumulator
__device__ float g_aggW[NN * LD];       // node_agg @ conv_W

__device__ __forceinline__ float4 relu4(float4 v) {
    v.x = fmaxf(v.x, 0.f); v.y = fmaxf(v.y, 0.f);
    v.z = fmaxf(v.z, 0.f); v.w = fmaxf(v.w, 0.f);
    return v;
}

__device__ __forceinline__ void red_add4(float* p, float4 v) {
    asm volatile("red.global.add.v4.f32 [%0], {%1,%2,%3,%4};"
                 :: "l"(p), "f"(v.x), "f"(v.y), "f"(v.z), "f"(v.w) : "memory");
}

// 64x128 = (64x128 @ 128x128) tile GEMM. 256 threads, each 8 rows x 4 cols.
__device__ __forceinline__ void gemm_tile128(const float* __restrict__ x_s,
                                             const float* __restrict__ w_s,
                                             float acc[8][4], int tx, int ty) {
#pragma unroll 4
    for (int k = 0; k < LD; k++) {
        float4 b = reinterpret_cast<const float4*>(w_s + k * LD)[tx];
#pragma unroll
        for (int i = 0; i < 8; i++) {
            float a = x_s[(ty * 8 + i) * LD + k];
            acc[i][0] = fmaf(a, b.x, acc[i][0]);
            acc[i][1] = fmaf(a, b.y, acc[i][1]);
            acc[i][2] = fmaf(a, b.z, acc[i][2]);
            acc[i][3] = fmaf(a, b.w, acc[i][3]);
        }
    }
}

__global__ void k_zero(float* out, int out_n) {
    int stride = gridDim.x * blockDim.x;
    for (int i = blockIdx.x * blockDim.x + threadIdx.x; i < NN * LD; i += stride)
        g_agg[i] = 0.f;
    for (int i = blockIdx.x * blockDim.x + threadIdx.x; i < out_n; i += stride)
        out[i] = 0.f;
}

// g_inl = node_feat @ Wn + bn
__global__ void __launch_bounds__(NT, 2)
k_node_linear(const float* __restrict__ nf, const float* __restrict__ W,
              const float* __restrict__ bias) {
    extern __shared__ float sm[];
    float* w_s = sm;                 // 128*128
    float* x_s = sm + LD * LD;       // 64*128
    float* b_s = x_s + TR * LD;      // 128
    int tid = threadIdx.x;
    int row0 = blockIdx.x * TR;

    for (int i = tid; i < LD * LD / 4; i += NT)
        reinterpret_cast<float4*>(w_s)[i] = reinterpret_cast<const float4*>(W)[i];
    if (tid < LD / 4)
        reinterpret_cast<float4*>(b_s)[tid] = reinterpret_cast<const float4*>(bias)[tid];
    for (int i = tid; i < TR * (LD / 4); i += NT) {
        int r = i >> 5, c4 = i & 31;
        int n = row0 + r;
        float4 v = make_float4(0.f, 0.f, 0.f, 0.f);
        if (n < NN) v = reinterpret_cast<const float4*>(nf + (long)n * LD)[c4];
        reinterpret_cast<float4*>(x_s + r * LD)[c4] = v;
    }
    __syncthreads();

    int tx = tid & 31, ty = tid >> 5;
    float acc[8][4] = {};
    gemm_tile128(x_s, w_s, acc, tx, ty);
    float4 bb = reinterpret_cast<const float4*>(b_s)[tx];
#pragma unroll
    for (int i = 0; i < 8; i++) {
        int n = row0 + ty * 8 + i;
        if (n < NN) {
            float4 o = make_float4(acc[i][0] + bb.x, acc[i][1] + bb.y,
                                   acc[i][2] + bb.z, acc[i][3] + bb.w);
            reinterpret_cast<float4*>(g_inl + (long)n * LD)[tx] = o;
        }
    }
}

// g_aggW = g_agg @ Wc ; then g_agg := 0 (ready for next scatter)
__global__ void __launch_bounds__(NT, 2)
k_node_aggW(const float* __restrict__ Wc) {
    extern __shared__ float sm[];
    float* w_s = sm;
    float* x_s = sm + LD * LD;
    int tid = threadIdx.x;
    int row0 = blockIdx.x * TR;

    for (int i = tid; i < LD * LD / 4; i += NT)
        reinterpret_cast<float4*>(w_s)[i] = reinterpret_cast<const float4*>(Wc)[i];
    const float4 z4 = make_float4(0.f, 0.f, 0.f, 0.f);
    for (int i = tid; i < TR * (LD / 4); i += NT) {
        int r = i >> 5, c4 = i & 31;
        int n = row0 + r;
        float4 v = z4;
        if (n < NN) {
            v = reinterpret_cast<const float4*>(g_agg + (long)n * LD)[c4];
            reinterpret_cast<float4*>(g_agg + (long)n * LD)[c4] = z4;
        }
        reinterpret_cast<float4*>(x_s + r * LD)[c4] = v;
    }
    __syncthreads();

    int tx = tid & 31, ty = tid >> 5;
    float acc[8][4] = {};
    gemm_tile128(x_s, w_s, acc, tx, ty);
#pragma unroll
    for (int i = 0; i < 8; i++) {
        int n = row0 + ty * 8 + i;
        if (n < NN)
            reinterpret_cast<float4*>(g_aggW + (long)n * LD)[tx] =
                make_float4(acc[i][0], acc[i][1], acc[i][2], acc[i][3]);
    }
}

// Prologue per edge tile: im = inl[src] + ef@We + be ; x = relu(im);
// g_curW = x @ Wc ; g_agg[dst] += x
__global__ void __launch_bounds__(NT)
k_im(const float* __restrict__ ef, const float* __restrict__ We,
     const float* __restrict__ be, const float* __restrict__ Wc,
     const int* __restrict__ esrc, const int* __restrict__ edst) {
    extern __shared__ float sm[];
    float* w_s  = sm;                          // conv_W 128*128
    float* we_s = w_s + LD * LD;               // 32*128
    float* x_s  = we_s + FED * LD;             // 64*128
    float* ef_s = x_s + TR * LD;               // 64*32
    float* be_s = ef_s + TR * FED;             // 128
    int* src_s  = reinterpret_cast<int*>(be_s + LD);
    int* dst_s  = src_s + TR;
    int tid = threadIdx.x;
    int row0 = blockIdx.x * TR;

    for (int i = tid; i < LD * LD / 4; i += NT)
        reinterpret_cast<float4*>(w_s)[i] = reinterpret_cast<const float4*>(Wc)[i];
    for (int i = tid; i < FED * LD / 4; i += NT)
        reinterpret_cast<float4*>(we_s)[i] = reinterpret_cast<const float4*>(We)[i];
    for (int i = tid; i < TR * FED / 4; i += NT)
        reinterpret_cast<float4*>(ef_s)[i] =
            reinterpret_cast<const float4*>(ef + (long)row0 * FED)[i];
    if (tid < LD / 4)
        reinterpret_cast<float4*>(be_s)[tid] = reinterpret_cast<const float4*>(be)[tid];
    if (tid < TR) src_s[tid] = esrc[row0 + tid];
    else if (tid < 2 * TR) dst_s[tid - TR] = edst[row0 + tid - TR];
    __syncthreads();

#pragma unroll
    for (int ii = 0; ii < 8; ii++) {
        int j = tid + NT * ii;          // warp-uniform row, lane = c4
        int r = j >> 5, c4 = j & 31;
        int e = row0 + r;
        float4 a = reinterpret_cast<const float4*>(g_inl + (long)src_s[r] * LD)[c4];
        float4 bb = reinterpret_cast<const float4*>(be_s)[c4];
        float4 acc = make_float4(a.x + bb.x, a.y + bb.y, a.z + bb.z, a.w + bb.w);
#pragma unroll
        for (int k = 0; k < FED; k++) {
            float s = ef_s[r * FED + k];
            float4 wv = reinterpret_cast<const float4*>(we_s + k * LD)[c4];
            acc.x = fmaf(s, wv.x, acc.x); acc.y = fmaf(s, wv.y, acc.y);
            acc.z = fmaf(s, wv.z, acc.z); acc.w = fmaf(s, wv.w, acc.w);
        }
        reinterpret_cast<float4*>(g_im + (long)e * LD)[c4] = acc;
        float4 x = relu4(acc);
        reinterpret_cast<float4*>(x_s + r * LD)[c4] = x;
        red_add4(g_agg + (long)dst_s[r] * LD + c4 * 4, x);
    }
    __syncthreads();

    int tx = tid & 31, ty = tid >> 5;
    float acc[8][4] = {};
    gemm_tile128(x_s, w_s, acc, tx, ty);
#pragma unroll
    for (int i = 0; i < 8; i++) {
        int e = row0 + ty * 8 + i;
        reinterpret_cast<float4*>(g_curW + (long)e * LD)[tx] =
            make_float4(acc[i][0], acc[i][1], acc[i][2], acc[i][3]);
    }
}

// One BP iteration per edge tile:
// x = relu(aggW[src] - curW[e^1] + im + bc) ; agg[dst] += x ; curW = x @ Wc (unless last)
__global__ void __launch_bounds__(NT, 2)
k_iter(const float* __restrict__ Wc, const float* __restrict__ bc,
       const int* __restrict__ esrc, const int* __restrict__ edst, int last) {
    extern __shared__ float sm[];
    float* w_s = sm;
    float* x_s = sm + LD * LD;
    float* b_s = x_s + TR * LD;
    int* src_s = reinterpret_cast<int*>(b_s + LD);
    int* dst_s = src_s + TR;
    int tid = threadIdx.x;
    int row0 = blockIdx.x * TR;

    for (int i = tid; i < LD * LD / 4; i += NT)
        reinterpret_cast<float4*>(w_s)[i] = reinterpret_cast<const float4*>(Wc)[i];
    if (tid < LD / 4)
        reinterpret_cast<float4*>(b_s)[tid] = reinterpret_cast<const float4*>(bc)[tid];
    if (tid < TR) src_s[tid] = esrc[row0 + tid];
    else if (tid < 2 * TR) dst_s[tid - TR] = edst[row0 + tid - TR];
    __syncthreads();

#pragma unroll
    for (int ii = 0; ii < 8; ii++) {
        int j = tid + NT * ii;
        int r = j >> 5, c4 = j & 31;
        int e = row0 + r;
        int erev = e ^ 1;               // reverse edge lives in this tile
        float4 aw = reinterpret_cast<const float4*>(g_aggW + (long)src_s[r] * LD)[c4];
        float4 cw = reinterpret_cast<const float4*>(g_curW + (long)erev * LD)[c4];
        float4 im = reinterpret_cast<const float4*>(g_im + (long)e * LD)[c4];
        float4 bb = reinterpret_cast<const float4*>(b_s)[c4];
        float4 x;
        x.x = fmaxf(aw.x - cw.x + im.x + bb.x, 0.f);
        x.y = fmaxf(aw.y - cw.y + im.y + bb.y, 0.f);
        x.z = fmaxf(aw.z - cw.z + im.z + bb.z, 0.f);
        x.w = fmaxf(aw.w - cw.w + im.w + bb.w, 0.f);
        reinterpret_cast<float4*>(x_s + r * LD)[c4] = x;
        red_add4(g_agg + (long)dst_s[r] * LD + c4 * 4, x);
    }
    __syncthreads();   // all curW reads done; all x_s written

    if (!last) {
        int tx = tid & 31, ty = tid >> 5;
        float acc[8][4] = {};
        gemm_tile128(x_s, w_s, acc, tx, ty);
#pragma unroll
        for (int i = 0; i < 8; i++) {
            int e = row0 + ty * 8 + i;
            reinterpret_cast<float4*>(g_curW + (long)e * LD)[tx] =
                make_float4(acc[i][0], acc[i][1], acc[i][2], acc[i][3]);
        }
    }
}

// Epilogue: h = relu(agg) ; y = relu(h @ Wo + bo) ; out[graph] += y
__global__ void __launch_bounds__(NT, 2)
k_out(const float* __restrict__ Wo, const float* __restrict__ bo,
      const int* __restrict__ gids, float* __restrict__ out) {
    extern __shared__ float sm[];
    float* w_s = sm;
    float* x_s = sm + LD * LD;
    float* b_s = x_s + TR * LD;
    int* gid_s = reinterpret_cast<int*>(b_s + LD);
    int tid = threadIdx.x;
    int row0 = blockIdx.x * TR;

    for (int i = tid; i < LD * LD / 4; i += NT)
        reinterpret_cast<float4*>(w_s)[i] = reinterpret_cast<const float4*>(Wo)[i];
    if (tid < LD / 4)
        reinterpret_cast<float4*>(b_s)[tid] = reinterpret_cast<const float4*>(bo)[tid];
    if (tid < TR) {
        int n = row0 + tid;
        gid_s[tid] = (n < NN) ? gids[n] : 0;
    }
    for (int i = tid; i < TR * (LD / 4); i += NT) {
        int r = i >> 5, c4 = i & 31;
        int n = row0 + r;
        float4 v = make_float4(0.f, 0.f, 0.f, 0.f);
        if (n < NN)
            v = relu4(reinterpret_cast<const float4*>(g_agg + (long)n * LD)[c4]);
        reinterpret_cast<float4*>(x_s + r * LD)[c4] = v;
    }
    __syncthreads();

    int tx = tid & 31, ty = tid >> 5;
    float acc[8][4] = {};
    gemm_tile128(x_s, w_s, acc, tx, ty);
    float4 bb = reinterpret_cast<const float4*>(b_s)[tx];
#pragma unroll
    for (int i = 0; i < 8; i++) {
        int r = ty * 8 + i;
        int n = row0 + r;
        if (n < NN) {
            float4 y = make_float4(fmaxf(acc[i][0] + bb.x, 0.f),
                                   fmaxf(acc[i][1] + bb.y, 0.f),
                                   fmaxf(acc[i][2] + bb.z, 0.f),
                                   fmaxf(acc[i][3] + bb.w, 0.f));
            red_add4(out + (long)gid_s[r] * LD + tx * 4, y);
        }
    }
}

extern "C" void kernel_launch(void* const* d_in, const int* in_sizes, int n_in,
                              void* d_out, int out_size) {
    const float* node_feat = (const float*)d_in[0];
    const float* edge_feat = (const float*)d_in[1];
    const float* Wn = (const float*)d_in[2];
    const float* bn = (const float*)d_in[3];
    const float* We = (const float*)d_in[4];
    const float* be = (const float*)d_in[5];
    const float* Wc = (const float*)d_in[6];
    const float* bc = (const float*)d_in[7];
    const float* Wo = (const float*)d_in[8];
    const float* bo = (const float*)d_in[9];
    const int* esrc = (const int*)d_in[10];
    const int* edst = (const int*)d_in[11];
    const int* gids = (const int*)d_in[12];
    float* out = (float*)d_out;

    const int SM_NODE = (LD * LD + TR * LD + LD) * 4;            // 98816
    const int SM_ITER = SM_NODE + 2 * TR * 4;                    // 99328
    const int SM_IM   = (LD * LD + FED * LD + TR * LD + TR * FED + LD) * 4 + 2 * TR * 4;
    const int SM_OUT  = SM_NODE + TR * 4;                        // 99072

    cudaFuncSetAttribute(k_node_linear, cudaFuncAttributeMaxDynamicSharedMemorySize, SM_NODE);
    cudaFuncSetAttribute(k_node_aggW,   cudaFuncAttributeMaxDynamicSharedMemorySize, SM_NODE);
    cudaFuncSetAttribute(k_im,          cudaFuncAttributeMaxDynamicSharedMemorySize, SM_IM);
    cudaFuncSetAttribute(k_iter,        cudaFuncAttributeMaxDynamicSharedMemorySize, SM_ITER);
    cudaFuncSetAttribute(k_out,         cudaFuncAttributeMaxDynamicSharedMemorySize, SM_OUT);

    k_zero<<<384, 256>>>(out, out_size);
    k_node_linear<<<NB_NODE, NT, SM_NODE>>>(node_feat, Wn, bn);
    k_im<<<NB_EDGE, NT, SM_IM>>>(edge_feat, We, be, Wc, esrc, edst);
    for (int t = 0; t < 3; t++) {
        k_node_aggW<<<NB_NODE, NT, SM_NODE>>>(Wc);
        k_iter<<<NB_EDGE, NT, SM_ITER>>>(Wc, bc, esrc, edst, (t == 2) ? 1 : 0);
    }
    k_out<<<NB_NODE, NT, SM_OUT>>>(Wo, bo, gids, out);
}